// round 13
// baseline (speedup 1.0000x reference)
#include <cuda_runtime.h>
#include <cuda_fp16.h>
#include <cstdint>
#include <math.h>

#define N_NODES 100000
#define N_EDGES 1000000
#define CAP 48                     // bucket capacity per row (Poisson(10) max ~30)

// ---------------- scratch (static device globals; no allocation) ----------------
__device__ __half g_H[(size_t)N_NODES * 128];   // [N][128] fp16 : x@W0 | x@W1
__device__ __half g_T[(size_t)N_NODES * 64];    // [N][64]  fp16 : A h1
__device__ float  g_deg1[N_NODES];              // A 1

// bucket sort scratch
__device__ int    g_cnt[N_NODES];               // per-row edge count (zeroed each call)
__device__ unsigned long long g_bucket[(size_t)N_NODES * CAP];  // {val:32|col:32}
__device__ int    g_spill_n;                    // overflow count (zeroed each call)
__device__ int2   g_spill_rc[N_EDGES];          // overflow {row, col}
__device__ float  g_spill_v[N_EDGES];           // overflow val

// ---------------- zero counters ----------------
__global__ void zero_kernel() {
    const int stride = gridDim.x * blockDim.x;
    for (int i = blockIdx.x * blockDim.x + threadIdx.x; i < N_NODES; i += stride)
        g_cnt[i] = 0;
    if (blockIdx.x == 0 && threadIdx.x == 0) g_spill_n = 0;
}

// ---------------- bucket scatter (4 edges/thread, packed col+val) ----------------
__global__ void scatter_kernel(const int* __restrict__ ei, const float* __restrict__ ea) {
    const int q = blockIdx.x * blockDim.x + threadIdx.x;
    if (q >= N_EDGES / 4) return;
    int4 r = __ldg(&((const int4*)ei)[q]);
    int4 c = __ldg(&((const int4*)(ei + N_EDGES))[q]);
    float4 v = __ldg(&((const float4*)ea)[q]);
    int rr[4] = {r.x, r.y, r.z, r.w};
    int cc[4] = {c.x, c.y, c.z, c.w};
    float vv[4] = {v.x, v.y, v.z, v.w};
    int pos[4];
#pragma unroll
    for (int k = 0; k < 4; k++) pos[k] = atomicAdd(&g_cnt[rr[k]], 1);
#pragma unroll
    for (int k = 0; k < 4; k++) {
        unsigned long long pk =
            ((unsigned long long)__float_as_uint(vv[k]) << 32) | (unsigned int)cc[k];
        if (pos[k] < CAP) {
            g_bucket[(size_t)rr[k] * CAP + pos[k]] = pk;
        } else {
            int idx = atomicAdd(&g_spill_n, 1);
            g_spill_rc[idx] = make_int2(rr[k], cc[k]);
            g_spill_v[idx] = vv[k];
        }
    }
}

// ---------------- tensor-core GEMM: H = fp16( x @ [W0|W1] ) ----------------
#define SM_STRIDE 136

__device__ __forceinline__ unsigned int smem_u32(const void* p) {
    unsigned int a;
    asm("{ .reg .u64 t; cvta.to.shared.u64 t, %1; cvt.u32.u64 %0, t; }"
        : "=r"(a) : "l"(p));
    return a;
}

__global__ __launch_bounds__(256) void gemm_kernel(const float* __restrict__ x,
                                                   const float* __restrict__ W0,
                                                   const float* __restrict__ W1) {
    extern __shared__ __half smem_dyn[];
    __half* As = smem_dyn;                         // [128][SM_STRIDE]
    __half* Bs = smem_dyn + 128 * SM_STRIDE;       // [128][SM_STRIDE]

    const int tid = threadIdx.x;
    const int r0 = blockIdx.x * 128;

    const float4* W04 = (const float4*)W0;
    const float4* W14 = (const float4*)W1;
    for (int i = tid; i < 2048; i += 256) {
        int k = i >> 4, c4 = i & 15;
        float4 v0 = __ldg(&W04[i]);
        float4 v1 = __ldg(&W14[i]);
        __half2 a01 = __floats2half2_rn(v0.x, v0.y);
        __half2 a23 = __floats2half2_rn(v0.z, v0.w);
        __half2 b01 = __floats2half2_rn(v1.x, v1.y);
        __half2 b23 = __floats2half2_rn(v1.z, v1.w);
        *(uint2*)&Bs[k * SM_STRIDE + c4 * 4] =
            make_uint2(*(unsigned int*)&a01, *(unsigned int*)&a23);
        *(uint2*)&Bs[k * SM_STRIDE + 64 + c4 * 4] =
            make_uint2(*(unsigned int*)&b01, *(unsigned int*)&b23);
    }
    const float4* x4 = (const float4*)x;
    for (int i = tid; i < 4096; i += 256) {
        int r = i >> 5, c4 = i & 31;
        float4 v = (r0 + r < N_NODES) ? __ldg(&x4[(size_t)(r0 + r) * 32 + c4])
                                      : make_float4(0.f, 0.f, 0.f, 0.f);
        __half2 h01 = __floats2half2_rn(v.x, v.y);
        __half2 h23 = __floats2half2_rn(v.z, v.w);
        *(uint2*)&As[r * SM_STRIDE + c4 * 4] =
            make_uint2(*(unsigned int*)&h01, *(unsigned int*)&h23);
    }
    __syncthreads();

    const int w = tid >> 5;
    const int lane = tid & 31;
    const unsigned int As_u = smem_u32(As);
    const unsigned int Bs_u = smem_u32(Bs);

    const int arow = w * 16 + (lane & 7) + (lane & 8);
    const int acol8 = (lane >> 4) & 1;
    const int bls = lane & 15;

    float acc[16][4];
#pragma unroll
    for (int n = 0; n < 16; n++)
#pragma unroll
        for (int c = 0; c < 4; c++) acc[n][c] = 0.f;

#pragma unroll
    for (int kk = 0; kk < 8; kk++) {
        unsigned int a0, a1, a2, a3;
        unsigned int addrA = As_u + (unsigned int)((arow * SM_STRIDE + kk * 16 + acol8 * 8) * 2);
        asm volatile("ldmatrix.sync.aligned.m8n8.x4.shared.b16 {%0,%1,%2,%3}, [%4];"
                     : "=r"(a0), "=r"(a1), "=r"(a2), "=r"(a3) : "r"(addrA));
        unsigned int addrB0 = Bs_u + (unsigned int)(((kk * 16 + bls) * SM_STRIDE) * 2);
#pragma unroll
        for (int n = 0; n < 16; n++) {
            unsigned int bm0, bm1;
            unsigned int addrB = addrB0 + (unsigned int)(n * 16);
            asm volatile("ldmatrix.sync.aligned.m8n8.x2.trans.shared.b16 {%0,%1}, [%2];"
                         : "=r"(bm0), "=r"(bm1) : "r"(addrB));
            asm volatile(
                "mma.sync.aligned.m16n8k16.row.col.f32.f16.f16.f32 "
                "{%0,%1,%2,%3}, {%4,%5,%6,%7}, {%8,%9}, {%0,%1,%2,%3};"
                : "+f"(acc[n][0]), "+f"(acc[n][1]), "+f"(acc[n][2]), "+f"(acc[n][3])
                : "r"(a0), "r"(a1), "r"(a2), "r"(a3), "r"(bm0), "r"(bm1));
        }
    }

    const int rA = r0 + w * 16 + (lane >> 2);
    const int colb = (lane & 3) * 2;
#pragma unroll
    for (int n = 0; n < 16; n++) {
        int col = n * 8 + colb;
        if (rA < N_NODES) {
            __half2 h = __floats2half2_rn(acc[n][0], acc[n][1]);
            *(__half2*)&g_H[(size_t)rA * 128 + col] = h;
        }
        if (rA + 8 < N_NODES) {
            __half2 h = __floats2half2_rn(acc[n][2], acc[n][3]);
            *(__half2*)&g_H[(size_t)(rA + 8) * 128 + col] = h;
        }
    }
}

// ---------------- host-side stream/event objects (created once at load) ----------
namespace {
struct ForkCtx {
    cudaStream_t s2;
    cudaEvent_t evF, evG;
    ForkCtx() {
        cudaStreamCreateWithFlags(&s2, cudaStreamNonBlocking);
        cudaEventCreateWithFlags(&evF, cudaEventDisableTiming);
        cudaEventCreateWithFlags(&evG, cudaEventDisableTiming);
        cudaFuncSetAttribute(gemm_kernel, cudaFuncAttributeMaxDynamicSharedMemorySize,
                             2 * 128 * SM_STRIDE * (int)sizeof(__half));
    }
};
ForkCtx g_fork;
}

// ---------------- SpMM helpers ----------------
__device__ __forceinline__ void unpack_edge(unsigned long long p, int& c, float& v) {
    c = (int)(unsigned int)p;
    v = __uint_as_float((unsigned int)(p >> 32));
}
__device__ __forceinline__ float4 ld_half4(const __half* p) {
    uint2 u = *(const uint2*)p;
    float2 a = __half22float2(*(__half2*)&u.x);
    float2 b = __half22float2(*(__half2*)&u.y);
    return make_float4(a.x, a.y, b.x, b.y);
}

// ---- pass 1 + hop0 epilogue: warp per row, 4-edge unroll, fp16 gathers -----------
// lanes 0-15 : hop0 features (cols 0..63) -> normalize+encode -> out[:,0:64]
// lanes 16-31: hop1 partial T = A h1      -> fp16 store to g_T
__global__ __launch_bounds__(256) void spmm1_kernel(const float* __restrict__ b0,
                                                    const float* __restrict__ fc0,
                                                    const float* __restrict__ bf0,
                                                    float* __restrict__ out) {
    const int w = (blockIdx.x * 256 + threadIdx.x) >> 5;
    const int lane = threadIdx.x & 31;
    if (w >= N_NODES) return;
    const int cnt = g_cnt[w];
    const int n = (cnt < CAP) ? cnt : CAP;
    const unsigned long long* bucket = &g_bucket[(size_t)w * CAP];

    float4 acc = make_float4(0.f, 0.f, 0.f, 0.f);
    float deg = 0.f;
    int i = 0;
    for (; i + 4 <= n; i += 4) {
        int c0, c1, c2, c3;
        float v0, v1, v2, v3;
        unpack_edge(bucket[i + 0], c0, v0);
        unpack_edge(bucket[i + 1], c1, v1);
        unpack_edge(bucket[i + 2], c2, v2);
        unpack_edge(bucket[i + 3], c3, v3);
        float4 h0 = ld_half4(&g_H[(size_t)c0 * 128 + lane * 4]);
        float4 h1 = ld_half4(&g_H[(size_t)c1 * 128 + lane * 4]);
        float4 h2 = ld_half4(&g_H[(size_t)c2 * 128 + lane * 4]);
        float4 h3 = ld_half4(&g_H[(size_t)c3 * 128 + lane * 4]);
        acc.x += v0 * h0.x + v1 * h1.x + v2 * h2.x + v3 * h3.x;
        acc.y += v0 * h0.y + v1 * h1.y + v2 * h2.y + v3 * h3.y;
        acc.z += v0 * h0.z + v1 * h1.z + v2 * h2.z + v3 * h3.z;
        acc.w += v0 * h0.w + v1 * h1.w + v2 * h2.w + v3 * h3.w;
        deg += (v0 + v1) + (v2 + v3);
    }
    if (i + 2 <= n) {
        int c0, c1;
        float v0, v1;
        unpack_edge(bucket[i + 0], c0, v0);
        unpack_edge(bucket[i + 1], c1, v1);
        float4 h0 = ld_half4(&g_H[(size_t)c0 * 128 + lane * 4]);
        float4 h1 = ld_half4(&g_H[(size_t)c1 * 128 + lane * 4]);
        acc.x += v0 * h0.x + v1 * h1.x;
        acc.y += v0 * h0.y + v1 * h1.y;
        acc.z += v0 * h0.z + v1 * h1.z;
        acc.w += v0 * h0.w + v1 * h1.w;
        deg += v0 + v1;
        i += 2;
    }
    if (i < n) {
        int c0;
        float v0;
        unpack_edge(bucket[i], c0, v0);
        float4 h0 = ld_half4(&g_H[(size_t)c0 * 128 + lane * 4]);
        acc.x += v0 * h0.x;
        acc.y += v0 * h0.y;
        acc.z += v0 * h0.z;
        acc.w += v0 * h0.w;
        deg += v0;
    }
    // overflow (rare path; empty in practice)
    if (cnt > CAP) {
        const int L = g_spill_n;
        for (int j = 0; j < L; j++) {
            int2 rc = g_spill_rc[j];
            if (rc.x == w) {
                float v = g_spill_v[j];
                float4 h = ld_half4(&g_H[(size_t)rc.y * 128 + lane * 4]);
                acc.x += v * h.x;
                acc.y += v * h.y;
                acc.z += v * h.z;
                acc.w += v * h.w;
                deg += v;
            }
        }
    }

    const int l4 = (lane & 15) * 4;
    float inv = (deg > 0.f) ? (1.f / deg) : 0.f;
    float4 y;
    y.x = acc.x * inv + __ldg(&b0[l4 + 0]);
    y.y = acc.y * inv + __ldg(&b0[l4 + 1]);
    y.z = acc.z * inv + __ldg(&b0[l4 + 2]);
    y.w = acc.w * inv + __ldg(&b0[l4 + 3]);
    float dot = y.x * __ldg(&fc0[l4 + 0]) + y.y * __ldg(&fc0[l4 + 1]) +
                y.z * __ldg(&fc0[l4 + 2]) + y.w * __ldg(&fc0[l4 + 3]);
#pragma unroll
    for (int o = 8; o; o >>= 1) dot += __shfl_xor_sync(0xffffffffu, dot, o);
    float g = 1.f / (1.f + expf(-(dot + __ldg(&bf0[0]))));

    if (lane < 16) {
        float4 o;
        o.x = (y.x > 0.f) ? y.x : g * y.x;
        o.y = (y.y > 0.f) ? y.y : g * y.y;
        o.z = (y.z > 0.f) ? y.z : g * y.z;
        o.w = (y.w > 0.f) ? y.w : g * y.w;
        *(float4*)&out[(size_t)w * 128 + l4] = o;
    } else {
        __half2 t0 = __floats2half2_rn(acc.x, acc.y);
        __half2 t1 = __floats2half2_rn(acc.z, acc.w);
        *(uint2*)&g_T[(size_t)w * 64 + l4] =
            make_uint2(*(unsigned int*)&t0, *(unsigned int*)&t1);
    }
    if (lane == 0) g_deg1[w] = deg;
}

// ---- pass 2 + hop1 epilogue: warp per row, 4-edge unroll, fp16 T gathers ----------
// Also re-zeroes g_cnt[w] (last consumer) so the next call starts clean.
__global__ __launch_bounds__(256) void spmm2_kernel(const float* __restrict__ b1,
                                                    const float* __restrict__ fc1,
                                                    const float* __restrict__ bf1,
                                                    float* __restrict__ out) {
    const int w = (blockIdx.x * 256 + threadIdx.x) >> 5;
    const int lane = threadIdx.x & 31;
    if (w >= N_NODES) return;
    const int cnt = g_cnt[w];
    const int n = (cnt < CAP) ? cnt : CAP;
    const unsigned long long* bucket = &g_bucket[(size_t)w * CAP];

    float2 acc = make_float2(0.f, 0.f);
    float deg = 0.f;
    int i = 0;
    for (; i + 4 <= n; i += 4) {
        int c0, c1, c2, c3;
        float v0, v1, v2, v3;
        unpack_edge(bucket[i + 0], c0, v0);
        unpack_edge(bucket[i + 1], c1, v1);
        unpack_edge(bucket[i + 2], c2, v2);
        unpack_edge(bucket[i + 3], c3, v3);
        unsigned int u0 = *(const unsigned int*)&g_T[(size_t)c0 * 64 + lane * 2];
        unsigned int u1 = *(const unsigned int*)&g_T[(size_t)c1 * 64 + lane * 2];
        unsigned int u2 = *(const unsigned int*)&g_T[(size_t)c2 * 64 + lane * 2];
        unsigned int u3 = *(const unsigned int*)&g_T[(size_t)c3 * 64 + lane * 2];
        float d0 = __ldg(&g_deg1[c0]);
        float d1 = __ldg(&g_deg1[c1]);
        float d2 = __ldg(&g_deg1[c2]);
        float d3 = __ldg(&g_deg1[c3]);
        float2 t0 = __half22float2(*(__half2*)&u0);
        float2 t1 = __half22float2(*(__half2*)&u1);
        float2 t2 = __half22float2(*(__half2*)&u2);
        float2 t3 = __half22float2(*(__half2*)&u3);
        acc.x += v0 * t0.x + v1 * t1.x + v2 * t2.x + v3 * t3.x;
        acc.y += v0 * t0.y + v1 * t1.y + v2 * t2.y + v3 * t3.y;
        deg += (v0 * d0 + v1 * d1) + (v2 * d2 + v3 * d3);
    }
    if (i + 2 <= n) {
        int c0, c1;
        float v0, v1;
        unpack_edge(bucket[i + 0], c0, v0);
        unpack_edge(bucket[i + 1], c1, v1);
        unsigned int u0 = *(const unsigned int*)&g_T[(size_t)c0 * 64 + lane * 2];
        unsigned int u1 = *(const unsigned int*)&g_T[(size_t)c1 * 64 + lane * 2];
        float2 t0 = __half22float2(*(__half2*)&u0);
        float2 t1 = __half22float2(*(__half2*)&u1);
        acc.x += v0 * t0.x + v1 * t1.x;
        acc.y += v0 * t0.y + v1 * t1.y;
        deg += v0 * __ldg(&g_deg1[c0]) + v1 * __ldg(&g_deg1[c1]);
        i += 2;
    }
    if (i < n) {
        int c0;
        float v0;
        unpack_edge(bucket[i], c0, v0);
        unsigned int u0 = *(const unsigned int*)&g_T[(size_t)c0 * 64 + lane * 2];
        float2 t0 = __half22float2(*(__half2*)&u0);
        acc.x += v0 * t0.x;
        acc.y += v0 * t0.y;
        deg += v0 * __ldg(&g_deg1[c0]);
    }
    // overflow (rare path)
    if (cnt > CAP) {
        const int L = g_spill_n;
        for (int j = 0; j < L; j++) {
            int2 rc = g_spill_rc[j];
            if (rc.x == w) {
                float v = g_spill_v[j];
                unsigned int u = *(const unsigned int*)&g_T[(size_t)rc.y * 64 + lane * 2];
                float2 t = __half22float2(*(__half2*)&u);
                acc.x += v * t.x;
                acc.y += v * t.y;
                deg += v * __ldg(&g_deg1[rc.y]);
            }
        }
    }

    float inv = (deg > 0.f) ? (1.f / deg) : 0.f;
    float2 y;
    y.x = acc.x * inv + __ldg(&b1[2 * lane]);
    y.y = acc.y * inv + __ldg(&b1[2 * lane + 1]);
    float dot = y.x * __ldg(&fc1[2 * lane]) + y.y * __ldg(&fc1[2 * lane + 1]);
#pragma unroll
    for (int o = 16; o; o >>= 1) dot += __shfl_xor_sync(0xffffffffu, dot, o);
    float g = 1.f / (1.f + expf(-(dot + __ldg(&bf1[0]))));

    float2 o;
    o.x = (y.x > 0.f) ? y.x : g * y.x;
    o.y = (y.y > 0.f) ? y.y : g * y.y;
    *(float2*)&out[(size_t)w * 128 + 64 + 2 * lane] = o;
}

// ---------------- launch ----------------
extern "C" void kernel_launch(void* const* d_in, const int* in_sizes, int n_in,
                              void* d_out, int out_size) {
    const float* x   = (const float*)d_in[0];
    const int*   ei  = (const int*)d_in[1];
    const float* ea  = (const float*)d_in[2];
    const float* W0  = (const float*)d_in[3];
    const float* b0  = (const float*)d_in[4];
    const float* W1  = (const float*)d_in[5];
    const float* b1  = (const float*)d_in[6];
    const float* fc0 = (const float*)d_in[7];
    const float* bf0 = (const float*)d_in[8];
    const float* fc1 = (const float*)d_in[9];
    const float* bf1 = (const float*)d_in[10];
    float* out = (float*)d_out;

    // Fork: GEMM on side stream, bucket build on main stream.
    cudaEventRecord(g_fork.evF, 0);
    cudaStreamWaitEvent(g_fork.s2, g_fork.evF, 0);

    const int gemm_smem = 2 * 128 * SM_STRIDE * (int)sizeof(__half);
    gemm_kernel<<<(N_NODES + 127) / 128, 256, gemm_smem, g_fork.s2>>>(x, W0, W1);
    cudaEventRecord(g_fork.evG, g_fork.s2);

    zero_kernel<<<392, 256>>>();
    scatter_kernel<<<(N_EDGES / 4 + 255) / 256, 256>>>(ei, ea);

    // Join: spmm1 needs both buckets (main) and g_H (side).
    cudaStreamWaitEvent(0, g_fork.evG, 0);

    spmm1_kernel<<<(N_NODES * 32 + 255) / 256, 256>>>(b0, fc0, bf0, out);
    spmm2_kernel<<<(N_NODES * 32 + 255) / 256, 256>>>(b1, fc1, bf1, out);
}

// round 14
// speedup vs baseline: 1.0660x; 1.0660x over previous
#include <cuda_runtime.h>
#include <cuda_fp16.h>
#include <cstdint>
#include <math.h>

#define N_NODES 100000
#define N_EDGES 1000000
#define SCAN_BLK 98               // ceil(100000 / 1024)

// ---------------- scratch (static device globals; no allocation) ----------------
__device__ __half g_H[(size_t)N_NODES * 128];   // [N][128] fp16 : x@W0 | x@W1
__device__ __half g_T[(size_t)N_NODES * 64];    // [N][64]  fp16 : A h1
__device__ float  g_deg1[N_NODES];              // A 1

// CSR build scratch (g_cnt zero at load; re-zeroed by scan1 each call)
__device__ int   g_cnt[N_NODES];
__device__ int   g_cur[N_NODES];                // scatter cursors (init = row ptr)
__device__ int   g_ptr[N_NODES + 1];            // row_ptr (exclusive)
__device__ int   g_blk[128];                    // block sums for scan
__device__ unsigned long long g_edge[N_EDGES];  // packed {val_bits:32 | col*256:32}

// ---------------- histogram of rows ----------------
__global__ void hist_kernel(const int* __restrict__ ei) {
    const int stride = gridDim.x * blockDim.x;
    const int4* R4 = (const int4*)ei;
    for (int i = blockIdx.x * blockDim.x + threadIdx.x; i < N_EDGES / 4; i += stride) {
        int4 r = __ldg(&R4[i]);
        atomicAdd(&g_cnt[r.x], 1);
        atomicAdd(&g_cnt[r.y], 1);
        atomicAdd(&g_cnt[r.z], 1);
        atomicAdd(&g_cnt[r.w], 1);
    }
}

// ---------------- scan stage 1: per-block exclusive scan; also re-zero g_cnt --------
__global__ __launch_bounds__(256) void scan1_kernel() {
    __shared__ int sh[256];
    const int t = threadIdx.x;
    const int base = blockIdx.x * 1024 + t * 4;
    int c0 = (base + 0 < N_NODES) ? g_cnt[base + 0] : 0;
    int c1 = (base + 1 < N_NODES) ? g_cnt[base + 1] : 0;
    int c2 = (base + 2 < N_NODES) ? g_cnt[base + 2] : 0;
    int c3 = (base + 3 < N_NODES) ? g_cnt[base + 3] : 0;
    if (base + 0 < N_NODES) g_cnt[base + 0] = 0;
    if (base + 1 < N_NODES) g_cnt[base + 1] = 0;
    if (base + 2 < N_NODES) g_cnt[base + 2] = 0;
    if (base + 3 < N_NODES) g_cnt[base + 3] = 0;
    int tsum = c0 + c1 + c2 + c3;
    sh[t] = tsum;
    __syncthreads();
    for (int off = 1; off < 256; off <<= 1) {
        int v = (t >= off) ? sh[t - off] : 0;
        __syncthreads();
        if (t >= off) sh[t] += v;
        __syncthreads();
    }
    int excl = (t > 0) ? sh[t - 1] : 0;
    if (t == 255) g_blk[blockIdx.x] = sh[255];
    if (base + 0 < N_NODES) g_ptr[base + 0] = excl;
    if (base + 1 < N_NODES) g_ptr[base + 1] = excl + c0;
    if (base + 2 < N_NODES) g_ptr[base + 2] = excl + c0 + c1;
    if (base + 3 < N_NODES) g_ptr[base + 3] = excl + c0 + c1 + c2;
}

// ---- scan stage 2+3 fused: redundant warp-scan of block sums + add offsets; ----
// ---- also initializes scatter cursors g_cur = row ptr.                      ----
__global__ __launch_bounds__(256) void scan3_kernel() {
    __shared__ int off[128];
    const int t = threadIdx.x;
    if (t < 32) {
        const int base = t * 4;
        int c0 = (base + 0 < SCAN_BLK) ? g_blk[base + 0] : 0;
        int c1 = (base + 1 < SCAN_BLK) ? g_blk[base + 1] : 0;
        int c2 = (base + 2 < SCAN_BLK) ? g_blk[base + 2] : 0;
        int c3 = (base + 3 < SCAN_BLK) ? g_blk[base + 3] : 0;
        int tsum = c0 + c1 + c2 + c3;
        int incl = tsum;
#pragma unroll
        for (int o = 1; o < 32; o <<= 1) {
            int u = __shfl_up_sync(0xffffffffu, incl, o);
            if (t >= o) incl += u;
        }
        int excl = incl - tsum;
        off[base + 0] = excl;
        off[base + 1] = excl + c0;
        off[base + 2] = excl + c0 + c1;
        off[base + 3] = excl + c0 + c1 + c2;
    }
    __syncthreads();
    const int stride = gridDim.x * blockDim.x;
    for (int i = blockIdx.x * blockDim.x + t; i < N_NODES; i += stride) {
        int p = g_ptr[i] + off[i >> 10];
        g_ptr[i] = p;
        g_cur[i] = p;
    }
    if (blockIdx.x == 0 && t == 0) g_ptr[N_NODES] = N_EDGES;
}

// ---------------- scatter edges into CSR order (4 edges/thread, packed) -----------
// stores col premultiplied by 256 (byte offset into g_H rows)
__global__ void scatter_kernel(const int* __restrict__ ei, const float* __restrict__ ea) {
    const int q = blockIdx.x * blockDim.x + threadIdx.x;
    if (q >= N_EDGES / 4) return;
    int4 r = __ldg(&((const int4*)ei)[q]);
    int4 c = __ldg(&((const int4*)(ei + N_EDGES))[q]);
    float4 v = __ldg(&((const float4*)ea)[q]);
    int p0 = atomicAdd(&g_cur[r.x], 1);
    int p1 = atomicAdd(&g_cur[r.y], 1);
    int p2 = atomicAdd(&g_cur[r.z], 1);
    int p3 = atomicAdd(&g_cur[r.w], 1);
    g_edge[p0] = ((unsigned long long)__float_as_uint(v.x) << 32) | ((unsigned int)c.x << 8);
    g_edge[p1] = ((unsigned long long)__float_as_uint(v.y) << 32) | ((unsigned int)c.y << 8);
    g_edge[p2] = ((unsigned long long)__float_as_uint(v.z) << 32) | ((unsigned int)c.z << 8);
    g_edge[p3] = ((unsigned long long)__float_as_uint(v.w) << 32) | ((unsigned int)c.w << 8);
}

// ---------------- tensor-core GEMM: H = fp16( x @ [W0|W1] ) ----------------
#define SM_STRIDE 136

__device__ __forceinline__ unsigned int smem_u32(const void* p) {
    unsigned int a;
    asm("{ .reg .u64 t; cvta.to.shared.u64 t, %1; cvt.u32.u64 %0, t; }"
        : "=r"(a) : "l"(p));
    return a;
}

__global__ __launch_bounds__(256) void gemm_kernel(const float* __restrict__ x,
                                                   const float* __restrict__ W0,
                                                   const float* __restrict__ W1) {
    extern __shared__ __half smem_dyn[];
    __half* As = smem_dyn;                         // [128][SM_STRIDE]
    __half* Bs = smem_dyn + 128 * SM_STRIDE;       // [128][SM_STRIDE]

    const int tid = threadIdx.x;
    const int r0 = blockIdx.x * 128;

    const float4* W04 = (const float4*)W0;
    const float4* W14 = (const float4*)W1;
    for (int i = tid; i < 2048; i += 256) {
        int k = i >> 4, c4 = i & 15;
        float4 v0 = __ldg(&W04[i]);
        float4 v1 = __ldg(&W14[i]);
        __half2 a01 = __floats2half2_rn(v0.x, v0.y);
        __half2 a23 = __floats2half2_rn(v0.z, v0.w);
        __half2 b01 = __floats2half2_rn(v1.x, v1.y);
        __half2 b23 = __floats2half2_rn(v1.z, v1.w);
        *(uint2*)&Bs[k * SM_STRIDE + c4 * 4] =
            make_uint2(*(unsigned int*)&a01, *(unsigned int*)&a23);
        *(uint2*)&Bs[k * SM_STRIDE + 64 + c4 * 4] =
            make_uint2(*(unsigned int*)&b01, *(unsigned int*)&b23);
    }
    const float4* x4 = (const float4*)x;
    for (int i = tid; i < 4096; i += 256) {
        int r = i >> 5, c4 = i & 31;
        float4 v = (r0 + r < N_NODES) ? __ldg(&x4[(size_t)(r0 + r) * 32 + c4])
                                      : make_float4(0.f, 0.f, 0.f, 0.f);
        __half2 h01 = __floats2half2_rn(v.x, v.y);
        __half2 h23 = __floats2half2_rn(v.z, v.w);
        *(uint2*)&As[r * SM_STRIDE + c4 * 4] =
            make_uint2(*(unsigned int*)&h01, *(unsigned int*)&h23);
    }
    __syncthreads();

    const int w = tid >> 5;
    const int lane = tid & 31;
    const unsigned int As_u = smem_u32(As);
    const unsigned int Bs_u = smem_u32(Bs);

    const int arow = w * 16 + (lane & 7) + (lane & 8);
    const int acol8 = (lane >> 4) & 1;
    const int bls = lane & 15;

    float acc[16][4];
#pragma unroll
    for (int n = 0; n < 16; n++)
#pragma unroll
        for (int c = 0; c < 4; c++) acc[n][c] = 0.f;

#pragma unroll
    for (int kk = 0; kk < 8; kk++) {
        unsigned int a0, a1, a2, a3;
        unsigned int addrA = As_u + (unsigned int)((arow * SM_STRIDE + kk * 16 + acol8 * 8) * 2);
        asm volatile("ldmatrix.sync.aligned.m8n8.x4.shared.b16 {%0,%1,%2,%3}, [%4];"
                     : "=r"(a0), "=r"(a1), "=r"(a2), "=r"(a3) : "r"(addrA));
        unsigned int addrB0 = Bs_u + (unsigned int)(((kk * 16 + bls) * SM_STRIDE) * 2);
#pragma unroll
        for (int n = 0; n < 16; n++) {
            unsigned int bm0, bm1;
            unsigned int addrB = addrB0 + (unsigned int)(n * 16);
            asm volatile("ldmatrix.sync.aligned.m8n8.x2.trans.shared.b16 {%0,%1}, [%2];"
                         : "=r"(bm0), "=r"(bm1) : "r"(addrB));
            asm volatile(
                "mma.sync.aligned.m16n8k16.row.col.f32.f16.f16.f32 "
                "{%0,%1,%2,%3}, {%4,%5,%6,%7}, {%8,%9}, {%0,%1,%2,%3};"
                : "+f"(acc[n][0]), "+f"(acc[n][1]), "+f"(acc[n][2]), "+f"(acc[n][3])
                : "r"(a0), "r"(a1), "r"(a2), "r"(a3), "r"(bm0), "r"(bm1));
        }
    }

    const int rA = r0 + w * 16 + (lane >> 2);
    const int colb = (lane & 3) * 2;
#pragma unroll
    for (int n = 0; n < 16; n++) {
        int col = n * 8 + colb;
        if (rA < N_NODES) {
            __half2 h = __floats2half2_rn(acc[n][0], acc[n][1]);
            *(__half2*)&g_H[(size_t)rA * 128 + col] = h;
        }
        if (rA + 8 < N_NODES) {
            __half2 h = __floats2half2_rn(acc[n][2], acc[n][3]);
            *(__half2*)&g_H[(size_t)(rA + 8) * 128 + col] = h;
        }
    }
}

// ---------------- host-side stream/event objects (created once at load) ----------
namespace {
struct ForkCtx {
    cudaStream_t s2;
    cudaEvent_t evF, evG;
    ForkCtx() {
        cudaStreamCreateWithFlags(&s2, cudaStreamNonBlocking);
        cudaEventCreateWithFlags(&evF, cudaEventDisableTiming);
        cudaEventCreateWithFlags(&evG, cudaEventDisableTiming);
        cudaFuncSetAttribute(gemm_kernel, cudaFuncAttributeMaxDynamicSharedMemorySize,
                             2 * 128 * SM_STRIDE * (int)sizeof(__half));
    }
};
ForkCtx g_fork;
}

// ---------------- SpMM helpers ----------------
__device__ __forceinline__ void unpack_edge(unsigned long long p, unsigned int& off,
                                            float& v) {
    off = (unsigned int)p;                         // col*256 (byte offset in g_H)
    v = __uint_as_float((unsigned int)(p >> 32));
}
__device__ __forceinline__ unsigned long long pack2(float a, float b) {
    unsigned long long r;
    asm("mov.b64 %0, {%1, %2};" : "=l"(r) : "f"(a), "f"(b));
    return r;
}
__device__ __forceinline__ void ffma2(unsigned long long& d, unsigned long long a,
                                      unsigned long long b) {
    asm("fma.rn.f32x2 %0, %1, %2, %0;" : "+l"(d) : "l"(a), "l"(b));
}
__device__ __forceinline__ float2 unpack2(unsigned long long v) {
    float2 f;
    asm("mov.b64 {%0, %1}, %2;" : "=f"(f.x), "=f"(f.y) : "l"(v));
    return f;
}
// load 4 halves at byte address, convert to 2 packed f32x2
__device__ __forceinline__ void ld_half4_p(const char* p, unsigned long long& lo,
                                           unsigned long long& hi) {
    uint2 u = *(const uint2*)p;
    float2 a = __half22float2(*(__half2*)&u.x);
    float2 b = __half22float2(*(__half2*)&u.y);
    lo = pack2(a.x, a.y);
    hi = pack2(b.x, b.y);
}

// ---- pass 1 + hop0 epilogue: warp per row, 4-edge unroll, fp16 gathers -----------
// lanes 0-15 : hop0 features (cols 0..63) -> normalize+encode -> out[:,0:64]
// lanes 16-31: hop1 partial T = A h1      -> fp16 store to g_T
__global__ __launch_bounds__(256) void spmm1_kernel(const float* __restrict__ b0,
                                                    const float* __restrict__ fc0,
                                                    const float* __restrict__ bf0,
                                                    float* __restrict__ out) {
    const int w = (blockIdx.x * 256 + threadIdx.x) >> 5;
    const int lane = threadIdx.x & 31;
    if (w >= N_NODES) return;
    const int s = g_ptr[w];
    const int e = g_ptr[w + 1];
    const char* Hb = (const char*)g_H + lane * 8;   // per-lane base (8 B per lane)

    unsigned long long acc01 = 0ull, acc23 = 0ull;
    float deg = 0.f;
    int i = s;
    for (; i + 4 <= e; i += 4) {
        unsigned int o0, o1, o2, o3;
        float v0, v1, v2, v3;
        unpack_edge(g_edge[i + 0], o0, v0);
        unpack_edge(g_edge[i + 1], o1, v1);
        unpack_edge(g_edge[i + 2], o2, v2);
        unpack_edge(g_edge[i + 3], o3, v3);
        unsigned long long h0l, h0h, h1l, h1h, h2l, h2h, h3l, h3h;
        ld_half4_p(Hb + o0, h0l, h0h);
        ld_half4_p(Hb + o1, h1l, h1h);
        ld_half4_p(Hb + o2, h2l, h2h);
        ld_half4_p(Hb + o3, h3l, h3h);
        unsigned long long vv0 = pack2(v0, v0);
        unsigned long long vv1 = pack2(v1, v1);
        unsigned long long vv2 = pack2(v2, v2);
        unsigned long long vv3 = pack2(v3, v3);
        ffma2(acc01, h0l, vv0); ffma2(acc23, h0h, vv0);
        ffma2(acc01, h1l, vv1); ffma2(acc23, h1h, vv1);
        ffma2(acc01, h2l, vv2); ffma2(acc23, h2h, vv2);
        ffma2(acc01, h3l, vv3); ffma2(acc23, h3h, vv3);
        deg += (v0 + v1) + (v2 + v3);
    }
    for (; i < e; i++) {
        unsigned int o0;
        float v0;
        unpack_edge(g_edge[i], o0, v0);
        unsigned long long h0l, h0h;
        ld_half4_p(Hb + o0, h0l, h0h);
        unsigned long long vv0 = pack2(v0, v0);
        ffma2(acc01, h0l, vv0);
        ffma2(acc23, h0h, vv0);
        deg += v0;
    }

    float2 a01 = unpack2(acc01);
    float2 a23 = unpack2(acc23);
    float4 acc = make_float4(a01.x, a01.y, a23.x, a23.y);

    const int l4 = (lane & 15) * 4;
    float inv = (deg > 0.f) ? (1.f / deg) : 0.f;
    float4 y;
    y.x = acc.x * inv + __ldg(&b0[l4 + 0]);
    y.y = acc.y * inv + __ldg(&b0[l4 + 1]);
    y.z = acc.z * inv + __ldg(&b0[l4 + 2]);
    y.w = acc.w * inv + __ldg(&b0[l4 + 3]);
    float dot = y.x * __ldg(&fc0[l4 + 0]) + y.y * __ldg(&fc0[l4 + 1]) +
                y.z * __ldg(&fc0[l4 + 2]) + y.w * __ldg(&fc0[l4 + 3]);
#pragma unroll
    for (int o = 8; o; o >>= 1) dot += __shfl_xor_sync(0xffffffffu, dot, o);
    float g = 1.f / (1.f + expf(-(dot + __ldg(&bf0[0]))));

    if (lane < 16) {
        float4 o;
        o.x = (y.x > 0.f) ? y.x : g * y.x;
        o.y = (y.y > 0.f) ? y.y : g * y.y;
        o.z = (y.z > 0.f) ? y.z : g * y.z;
        o.w = (y.w > 0.f) ? y.w : g * y.w;
        *(float4*)&out[(size_t)w * 128 + l4] = o;
    } else {
        __half2 t0 = __floats2half2_rn(acc.x, acc.y);
        __half2 t1 = __floats2half2_rn(acc.z, acc.w);
        *(uint2*)&g_T[(size_t)w * 64 + l4] =
            make_uint2(*(unsigned int*)&t0, *(unsigned int*)&t1);
    }
    if (lane == 0) g_deg1[w] = deg;
}

// ---- pass 2 + hop1 epilogue: warp per row, 4-edge unroll, fp16 T gathers ----------
__global__ __launch_bounds__(256) void spmm2_kernel(const float* __restrict__ b1,
                                                    const float* __restrict__ fc1,
                                                    const float* __restrict__ bf1,
                                                    float* __restrict__ out) {
    const int w = (blockIdx.x * 256 + threadIdx.x) >> 5;
    const int lane = threadIdx.x & 31;
    if (w >= N_NODES) return;
    const int s = g_ptr[w];
    const int e = g_ptr[w + 1];
    const char* Tb = (const char*)g_T + lane * 4;   // per-lane base (4 B per lane)

    float2 acc = make_float2(0.f, 0.f);
    float deg = 0.f;
    int i = s;
    for (; i + 4 <= e; i += 4) {
        unsigned int o0, o1, o2, o3;
        float v0, v1, v2, v3;
        unpack_edge(g_edge[i + 0], o0, v0);
        unpack_edge(g_edge[i + 1], o1, v1);
        unpack_edge(g_edge[i + 2], o2, v2);
        unpack_edge(g_edge[i + 3], o3, v3);
        unsigned int u0 = *(const unsigned int*)(Tb + (o0 >> 1));
        unsigned int u1 = *(const unsigned int*)(Tb + (o1 >> 1));
        unsigned int u2 = *(const unsigned int*)(Tb + (o2 >> 1));
        unsigned int u3 = *(const unsigned int*)(Tb + (o3 >> 1));
        float d0 = __ldg(&g_deg1[o0 >> 8]);
        float d1 = __ldg(&g_deg1[o1 >> 8]);
        float d2 = __ldg(&g_deg1[o2 >> 8]);
        float d3 = __ldg(&g_deg1[o3 >> 8]);
        float2 t0 = __half22float2(*(__half2*)&u0);
        float2 t1 = __half22float2(*(__half2*)&u1);
        float2 t2 = __half22float2(*(__half2*)&u2);
        float2 t3 = __half22float2(*(__half2*)&u3);
        acc.x += v0 * t0.x + v1 * t1.x + v2 * t2.x + v3 * t3.x;
        acc.y += v0 * t0.y + v1 * t1.y + v2 * t2.y + v3 * t3.y;
        deg += (v0 * d0 + v1 * d1) + (v2 * d2 + v3 * d3);
    }
    for (; i < e; i++) {
        unsigned int o0;
        float v0;
        unpack_edge(g_edge[i], o0, v0);
        unsigned int u0 = *(const unsigned int*)(Tb + (o0 >> 1));
        float2 t0 = __half22float2(*(__half2*)&u0);
        acc.x += v0 * t0.x;
        acc.y += v0 * t0.y;
        deg += v0 * __ldg(&g_deg1[o0 >> 8]);
    }

    float inv = (deg > 0.f) ? (1.f / deg) : 0.f;
    float2 y;
    y.x = acc.x * inv + __ldg(&b1[2 * lane]);
    y.y = acc.y * inv + __ldg(&b1[2 * lane + 1]);
    float dot = y.x * __ldg(&fc1[2 * lane]) + y.y * __ldg(&fc1[2 * lane + 1]);
#pragma unroll
    for (int o = 16; o; o >>= 1) dot += __shfl_xor_sync(0xffffffffu, dot, o);
    float g = 1.f / (1.f + expf(-(dot + __ldg(&bf1[0]))));

    float2 o;
    o.x = (y.x > 0.f) ? y.x : g * y.x;
    o.y = (y.y > 0.f) ? y.y : g * y.y;
    *(float2*)&out[(size_t)w * 128 + 64 + 2 * lane] = o;
}

// ---------------- launch ----------------
extern "C" void kernel_launch(void* const* d_in, const int* in_sizes, int n_in,
                              void* d_out, int out_size) {
    const float* x   = (const float*)d_in[0];
    const int*   ei  = (const int*)d_in[1];
    const float* ea  = (const float*)d_in[2];
    const float* W0  = (const float*)d_in[3];
    const float* b0  = (const float*)d_in[4];
    const float* W1  = (const float*)d_in[5];
    const float* b1  = (const float*)d_in[6];
    const float* fc0 = (const float*)d_in[7];
    const float* bf0 = (const float*)d_in[8];
    const float* fc1 = (const float*)d_in[9];
    const float* bf1 = (const float*)d_in[10];
    float* out = (float*)d_out;

    // Fork: GEMM on side stream, CSR build on main stream (independent chains).
    cudaEventRecord(g_fork.evF, 0);
    cudaStreamWaitEvent(g_fork.s2, g_fork.evF, 0);

    const int gemm_smem = 2 * 128 * SM_STRIDE * (int)sizeof(__half);
    gemm_kernel<<<(N_NODES + 127) / 128, 256, gemm_smem, g_fork.s2>>>(x, W0, W1);
    cudaEventRecord(g_fork.evG, g_fork.s2);

    hist_kernel<<<512, 256>>>(ei);
    scan1_kernel<<<SCAN_BLK, 256>>>();
    scan3_kernel<<<392, 256>>>();
    scatter_kernel<<<(N_EDGES / 4 + 255) / 256, 256>>>(ei, ea);

    // Join: spmm1 needs both the CSR (main stream) and g_H (side stream).
    cudaStreamWaitEvent(0, g_fork.evG, 0);

    spmm1_kernel<<<(N_NODES * 32 + 255) / 256, 256>>>(b0, fc0, bf0, out);
    spmm2_kernel<<<(N_NODES * 32 + 255) / 256, 256>>>(b1, fc1, bf1, out);
}